// round 1
// baseline (speedup 1.0000x reference)
#include <cuda_runtime.h>
#include <math.h>

#define DIMC   4096
#define NH     32
#define NKV    8
#define DH     128
#define BB     2
#define TSEQ   2048
#define BT     (BB * TSEQ)      // 4096 rows
#define KVDIM  (NKV * DH)       // 1024

// ---- scratch (device globals; no allocation allowed) ----
__device__ float g_Q[BT * DIMC];        // 64 MB
__device__ float g_K[BT * KVDIM];       // 16 MB
__device__ float g_V[BT * KVDIM];       // 16 MB
__device__ float g_O[BT * DIMC];        // 64 MB
__device__ float g_cos[TSEQ * 64];
__device__ float g_sin[TSEQ * 64];

// =====================================================================
// SGEMM: C[M,N] = A[M,K] @ B[K,N], row-major, all dims multiples of 128/8
// 128x128 tile, BK=8, 256 threads, 8x8 register tile per thread.
// =====================================================================
__global__ __launch_bounds__(256) void sgemm128(const float* __restrict__ A,
                                                const float* __restrict__ B,
                                                float* __restrict__ C,
                                                int M, int N, int K) {
    __shared__ float As[8][128];
    __shared__ float Bs[8][128];
    const int tid  = threadIdx.x;
    const int brow = blockIdx.y * 128;
    const int bcol = blockIdx.x * 128;

    const int arow = tid >> 1;            // A tile: 128 rows x 8 k
    const int acol = (tid & 1) << 2;
    const int brw  = tid >> 5;            // B tile: 8 k x 128 cols
    const int bcl  = (tid & 31) << 2;
    const int ty   = tid >> 4, tx = tid & 15;

    float acc[8][8];
#pragma unroll
    for (int i = 0; i < 8; i++)
#pragma unroll
        for (int j = 0; j < 8; j++) acc[i][j] = 0.f;

    const float* Aptr = A + (long)(brow + arow) * K + acol;
    const float* Bptr = B + (long)brw * N + bcol + bcl;

    for (int k0 = 0; k0 < K; k0 += 8) {
        float4 a4 = *(const float4*)(Aptr + k0);
        float4 b4 = *(const float4*)(Bptr + (long)k0 * N);
        As[acol + 0][arow] = a4.x;
        As[acol + 1][arow] = a4.y;
        As[acol + 2][arow] = a4.z;
        As[acol + 3][arow] = a4.w;
        *(float4*)&Bs[brw][bcl] = b4;
        __syncthreads();
#pragma unroll
        for (int kk = 0; kk < 8; kk++) {
            float ra[8], rb[8];
            *(float4*)&ra[0] = *(float4*)&As[kk][ty * 8];
            *(float4*)&ra[4] = *(float4*)&As[kk][ty * 8 + 4];
            *(float4*)&rb[0] = *(float4*)&Bs[kk][tx * 8];
            *(float4*)&rb[4] = *(float4*)&Bs[kk][tx * 8 + 4];
#pragma unroll
            for (int i = 0; i < 8; i++)
#pragma unroll
                for (int j = 0; j < 8; j++) acc[i][j] += ra[i] * rb[j];
        }
        __syncthreads();
    }
#pragma unroll
    for (int i = 0; i < 8; i++) {
        float* Crow = C + (long)(brow + ty * 8 + i) * N + bcol + tx * 8;
        *(float4*)Crow       = make_float4(acc[i][0], acc[i][1], acc[i][2], acc[i][3]);
        *(float4*)(Crow + 4) = make_float4(acc[i][4], acc[i][5], acc[i][6], acc[i][7]);
    }
}

// =====================================================================
// RoPE table (double precision angles, computed once per launch; cheap)
// =====================================================================
__global__ void rope_table() {
    int idx = blockIdx.x * 256 + threadIdx.x;
    if (idx >= TSEQ * 64) return;
    int d = idx & 63, t = idx >> 6;
    double inv = pow(10000.0, -(double)d / 64.0);
    double ang = (double)t * inv;
    g_cos[idx] = (float)cos(ang);
    g_sin[idx] = (float)sin(ang);
}

// x layout [B, T, nheads, 128]; rotate (d, d+64) pairs per head.
__global__ void rope_apply(float* __restrict__ x, int nheads, int total) {
    int idx = blockIdx.x * 256 + threadIdx.x;
    if (idx >= total) return;
    int d   = idx & 63;
    int bth = idx >> 6;                         // (b*T + t)*nheads + h
    int t   = (bth / nheads) % TSEQ;
    long base = (long)bth * 128 + d;
    float c = g_cos[t * 64 + d], s = g_sin[t * 64 + d];
    float x1 = x[base], x2 = x[base + 64];
    x[base]      = x1 * c - x2 * s;
    x[base + 64] = x1 * s + x2 * c;
}

// =====================================================================
// Flash attention (causal, GQA). One CTA = one (b, h, 64-row Q tile).
// smem: Qs[64][128], Kt[128][68] (transposed K), Vs[64][132], Ss[64][68],
//       m/l/corr[64]. Online softmax; O accumulated in registers (4x8/thr).
// =====================================================================
#define FLASH_SMEM_FLOATS (8192 + 8704 + 8448 + 4352 + 192)
#define FLASH_SMEM_BYTES  (FLASH_SMEM_FLOATS * 4)

__global__ __launch_bounds__(256) void flash_kernel() {
    extern __shared__ float sm[];
    float* Qs   = sm;              // 64*128
    float* Kt   = Qs + 8192;       // [128][68]
    float* Vs   = Kt + 8704;       // [64][132]
    float* Ss   = Vs + 8448;       // [64][68]
    float* mrow = Ss + 4352;       // 64
    float* lrow = mrow + 64;       // 64
    float* crow = lrow + 64;       // 64

    const int tid = threadIdx.x;
    const int qt  = blockIdx.x;            // q tile index (0..31)
    const int bh  = blockIdx.y;            // b*NH + h
    const int b   = bh >> 5;
    const int h   = bh & 31;
    const int kvh = h >> 2;                // group size 4
    const int q0  = qt * 64;
    const int ty  = tid >> 4, tx = tid & 15;
    const int r0  = ty * 4;                // 4 S/O rows per thread
    const int c0s = tx * 4;                // 4 S cols per thread
    const int c0v = tx * 8;                // 8 O cols per thread

    // load Q tile (64 x 128)
    const float* Qg = g_Q + ((long)(b * TSEQ + q0)) * DIMC + h * DH;
#pragma unroll
    for (int it = 0; it < 8; it++) {
        int idx = it * 256 + tid;
        int row = idx >> 5;
        int dg  = (idx & 31) << 2;
        *(float4*)&Qs[row * 128 + dg] = *(const float4*)&Qg[(long)row * DIMC + dg];
    }
    if (tid < 64) { mrow[tid] = -1e30f; lrow[tid] = 0.f; }

    float o[4][8];
#pragma unroll
    for (int i = 0; i < 4; i++)
#pragma unroll
        for (int j = 0; j < 8; j++) o[i][j] = 0.f;

    const float scale = 0.0883883476483184f;   // 1/sqrt(128)

    for (int kt = 0; kt <= qt; kt++) {
        const int k0 = kt * 64;
        const float* Kg = g_K + ((long)(b * TSEQ + k0)) * KVDIM + kvh * DH;
        const float* Vg = g_V + ((long)(b * TSEQ + k0)) * KVDIM + kvh * DH;
#pragma unroll
        for (int it = 0; it < 8; it++) {
            int idx  = it * 256 + tid;
            int krow = idx >> 5;
            int dg   = (idx & 31) << 2;
            float4 kv = *(const float4*)&Kg[(long)krow * KVDIM + dg];
            Kt[(dg + 0) * 68 + krow] = kv.x;
            Kt[(dg + 1) * 68 + krow] = kv.y;
            Kt[(dg + 2) * 68 + krow] = kv.z;
            Kt[(dg + 3) * 68 + krow] = kv.w;
            *(float4*)&Vs[krow * 132 + dg] = *(const float4*)&Vg[(long)krow * KVDIM + dg];
        }
        __syncthreads();

        // S = Q @ K^T  (4x4 per thread)
        float s[4][4];
#pragma unroll
        for (int i = 0; i < 4; i++)
#pragma unroll
            for (int j = 0; j < 4; j++) s[i][j] = 0.f;

        for (int d = 0; d < 128; d += 4) {
            float q[4][4];
#pragma unroll
            for (int i = 0; i < 4; i++)
                *(float4*)&q[i][0] = *(float4*)&Qs[(r0 + i) * 128 + d];
#pragma unroll
            for (int dd = 0; dd < 4; dd++) {
                float4 kv = *(float4*)&Kt[(d + dd) * 68 + c0s];
                float kj[4] = {kv.x, kv.y, kv.z, kv.w};
#pragma unroll
                for (int i = 0; i < 4; i++) {
                    float qi = q[i][dd];
#pragma unroll
                    for (int j = 0; j < 4; j++) s[i][j] += qi * kj[j];
                }
            }
        }

        // mask + scale + stage to smem
#pragma unroll
        for (int i = 0; i < 4; i++) {
            int qi = q0 + r0 + i;
#pragma unroll
            for (int j = 0; j < 4; j++) {
                int ki = k0 + c0s + j;
                Ss[(r0 + i) * 68 + c0s + j] = (ki <= qi) ? s[i][j] * scale : -1e30f;
            }
        }
        __syncthreads();

        // online softmax per row (threads 0..63)
        if (tid < 64) {
            float mo = mrow[tid];
            float mx = mo;
            float* srow = &Ss[tid * 68];
#pragma unroll 8
            for (int c = 0; c < 64; c++) mx = fmaxf(mx, srow[c]);
            float corr = __expf(mo - mx);
            float sum = 0.f;
#pragma unroll 8
            for (int c = 0; c < 64; c++) {
                float p = __expf(srow[c] - mx);
                srow[c] = p;
                sum += p;
            }
            mrow[tid] = mx;
            lrow[tid] = lrow[tid] * corr + sum;
            crow[tid] = corr;
        }
        __syncthreads();

        // rescale O, then O += P @ V
#pragma unroll
        for (int i = 0; i < 4; i++) {
            float cf = crow[r0 + i];
#pragma unroll
            for (int j = 0; j < 8; j++) o[i][j] *= cf;
        }
#pragma unroll 4
        for (int k = 0; k < 64; k++) {
            float4 v0 = *(float4*)&Vs[k * 132 + c0v];
            float4 v1 = *(float4*)&Vs[k * 132 + c0v + 4];
#pragma unroll
            for (int i = 0; i < 4; i++) {
                float p = Ss[(r0 + i) * 68 + k];
                o[i][0] += p * v0.x; o[i][1] += p * v0.y;
                o[i][2] += p * v0.z; o[i][3] += p * v0.w;
                o[i][4] += p * v1.x; o[i][5] += p * v1.y;
                o[i][6] += p * v1.z; o[i][7] += p * v1.w;
            }
        }
        __syncthreads();
    }

    // epilogue: normalize, write to g_O (layout [B, T, H*dh])
    float* Og = g_O + ((long)(b * TSEQ + q0)) * DIMC + h * DH;
#pragma unroll
    for (int i = 0; i < 4; i++) {
        float inv = 1.f / lrow[r0 + i];
        float4 w0 = make_float4(o[i][0] * inv, o[i][1] * inv, o[i][2] * inv, o[i][3] * inv);
        float4 w1 = make_float4(o[i][4] * inv, o[i][5] * inv, o[i][6] * inv, o[i][7] * inv);
        *(float4*)&Og[(long)(r0 + i) * DIMC + c0v]     = w0;
        *(float4*)&Og[(long)(r0 + i) * DIMC + c0v + 4] = w1;
    }
}

// =====================================================================
// launch
// =====================================================================
extern "C" void kernel_launch(void* const* d_in, const int* in_sizes, int n_in,
                              void* d_out, int out_size) {
    const float* X  = (const float*)d_in[0];
    const float* Wq = (const float*)d_in[1];
    const float* Wk = (const float*)d_in[2];
    const float* Wv = (const float*)d_in[3];
    const float* Wo = (const float*)d_in[4];
    float* out = (float*)d_out;

    float *Qp, *Kp, *Vp, *Op;
    cudaGetSymbolAddress((void**)&Qp, g_Q);
    cudaGetSymbolAddress((void**)&Kp, g_K);
    cudaGetSymbolAddress((void**)&Vp, g_V);
    cudaGetSymbolAddress((void**)&Op, g_O);

    cudaFuncSetAttribute(flash_kernel, cudaFuncAttributeMaxDynamicSharedMemorySize,
                         FLASH_SMEM_BYTES);

    // RoPE table
    rope_table<<<(TSEQ * 64 + 255) / 256, 256>>>();

    // projections
    sgemm128<<<dim3(DIMC / 128, BT / 128), 256>>>(X, Wq, Qp, BT, DIMC, DIMC);
    sgemm128<<<dim3(KVDIM / 128, BT / 128), 256>>>(X, Wk, Kp, BT, KVDIM, DIMC);
    sgemm128<<<dim3(KVDIM / 128, BT / 128), 256>>>(X, Wv, Vp, BT, KVDIM, DIMC);

    // RoPE
    {
        int totq = BT * NH * 64;
        rope_apply<<<(totq + 255) / 256, 256>>>(Qp, NH, totq);
        int totk = BT * NKV * 64;
        rope_apply<<<(totk + 255) / 256, 256>>>(Kp, NKV, totk);
    }

    // attention
    flash_kernel<<<dim3(TSEQ / 64, BB * NH), 256, FLASH_SMEM_BYTES>>>();

    // output projection
    sgemm128<<<dim3(DIMC / 128, BT / 128), 256>>>(Op, Wo, out, BT, DIMC, DIMC);
}

// round 2
// speedup vs baseline: 2.3112x; 2.3112x over previous
#include <cuda_runtime.h>
#include <math.h>
#include <stdint.h>

#define DIMC   4096
#define NH     32
#define NKV    8
#define DH     128
#define BB     2
#define TSEQ   2048
#define BT     (BB * TSEQ)      // 4096 rows
#define KVDIM  (NKV * DH)       // 1024

// ---- scratch (device globals; no allocation allowed) ----
__device__ float g_Q[BT * DIMC];        // 64 MB
__device__ float g_K[BT * KVDIM];       // 16 MB
__device__ float g_V[BT * KVDIM];       // 16 MB
__device__ float g_O[BT * DIMC];        // 64 MB
__device__ float g_cos[TSEQ * 64];
__device__ float g_sin[TSEQ * 64];

// =====================================================================
// TF32 tensor-core GEMM: C[M,N] = A[M,K] @ B[K,N], row-major.
// 128x128 CTA tile, BK=32, 256 threads (8 warps), warp tile 64x32 via
// mma.sync.m16n8k8.tf32. cp.async double-buffered smem pipeline.
// =====================================================================
#define GBM 128
#define GBN 128
#define GBK 32
#define ASTR 36     // As row stride (floats): [m][k], pad 4 -> conflict-free frag loads
#define BSTR 136    // Bs row stride (floats): [k][n], pad 8 -> conflict-free frag loads
#define GEMM_SMEM_BYTES ((2 * GBM * ASTR + 2 * GBK * BSTR) * 4)   // 71680 B

__device__ __forceinline__ uint32_t f2tf32(float f) {
    uint32_t u;
    asm("cvt.rna.tf32.f32 %0, %1;" : "=r"(u) : "f"(f));
    return u;
}

__device__ __forceinline__ void mma_tf32(float* c, const uint32_t* a, const uint32_t* b) {
    asm volatile(
        "mma.sync.aligned.m16n8k8.row.col.f32.tf32.tf32.f32 "
        "{%0,%1,%2,%3}, {%4,%5,%6,%7}, {%8,%9}, {%0,%1,%2,%3};"
        : "+f"(c[0]), "+f"(c[1]), "+f"(c[2]), "+f"(c[3])
        : "r"(a[0]), "r"(a[1]), "r"(a[2]), "r"(a[3]), "r"(b[0]), "r"(b[1]));
}

__device__ __forceinline__ void cpasync16(uint32_t dst, const void* src) {
    asm volatile("cp.async.cg.shared.global [%0], [%1], 16;" :: "r"(dst), "l"(src));
}

__global__ __launch_bounds__(256) void gemm_tf32(const float* __restrict__ A,
                                                 const float* __restrict__ B,
                                                 float* __restrict__ C,
                                                 int M, int N, int K) {
    extern __shared__ float smem[];
    float* As = smem;                      // [2][GBM][ASTR]
    float* Bs = smem + 2 * GBM * ASTR;     // [2][GBK][BSTR]

    const int tid  = threadIdx.x;
    const int brow = blockIdx.y * GBM;
    const int bcol = blockIdx.x * GBN;
    const int wid  = tid >> 5, lane = tid & 31;
    const int g    = lane >> 2, t = lane & 3;
    const int m_base = (wid & 1) * 64;
    const int n_base = (wid >> 1) * 32;

    // per-thread load coords
    const int a_r0 = tid >> 3;            // +32*i
    const int a_kc = (tid & 7) * 4;
    const int b_r0 = tid >> 5;            // +8*i
    const int b_nc = (tid & 31) * 4;

    float c[4][4][4];
#pragma unroll
    for (int mi = 0; mi < 4; mi++)
#pragma unroll
        for (int ni = 0; ni < 4; ni++)
#pragma unroll
            for (int r = 0; r < 4; r++) c[mi][ni][r] = 0.f;

    const int KT = K / GBK;

    // prefetch stage 0
    {
        float* as = As;
        float* bs = Bs;
#pragma unroll
        for (int i = 0; i < 4; i++) {
            int r = a_r0 + 32 * i;
            cpasync16((uint32_t)__cvta_generic_to_shared(&as[r * ASTR + a_kc]),
                      A + (long)(brow + r) * K + a_kc);
        }
#pragma unroll
        for (int i = 0; i < 4; i++) {
            int r = b_r0 + 8 * i;
            cpasync16((uint32_t)__cvta_generic_to_shared(&bs[r * BSTR + b_nc]),
                      B + (long)r * N + bcol + b_nc);
        }
        asm volatile("cp.async.commit_group;");
    }

    int s = 0;
    for (int kt = 0; kt < KT; kt++) {
        if (kt + 1 < KT) {
            const int k0 = (kt + 1) * GBK;
            float* as = As + (s ^ 1) * GBM * ASTR;
            float* bs = Bs + (s ^ 1) * GBK * BSTR;
#pragma unroll
            for (int i = 0; i < 4; i++) {
                int r = a_r0 + 32 * i;
                cpasync16((uint32_t)__cvta_generic_to_shared(&as[r * ASTR + a_kc]),
                          A + (long)(brow + r) * K + k0 + a_kc);
            }
#pragma unroll
            for (int i = 0; i < 4; i++) {
                int r = b_r0 + 8 * i;
                cpasync16((uint32_t)__cvta_generic_to_shared(&bs[r * BSTR + b_nc]),
                          B + (long)(k0 + r) * N + bcol + b_nc);
            }
            asm volatile("cp.async.commit_group;");
            asm volatile("cp.async.wait_group 1;");
        } else {
            asm volatile("cp.async.wait_group 0;");
        }
        __syncthreads();

        const float* as = As + s * GBM * ASTR;
        const float* bs = Bs + s * GBK * BSTR;
#pragma unroll
        for (int kk = 0; kk < GBK; kk += 8) {
            uint32_t af[4][4], bf[4][2];
#pragma unroll
            for (int mi = 0; mi < 4; mi++) {
                const float* p = &as[(m_base + 16 * mi + g) * ASTR + kk + t];
                af[mi][0] = f2tf32(p[0]);
                af[mi][1] = f2tf32(p[8 * ASTR]);
                af[mi][2] = f2tf32(p[4]);
                af[mi][3] = f2tf32(p[8 * ASTR + 4]);
            }
#pragma unroll
            for (int ni = 0; ni < 4; ni++) {
                const float* p = &bs[(kk + t) * BSTR + n_base + 8 * ni + g];
                bf[ni][0] = f2tf32(p[0]);
                bf[ni][1] = f2tf32(p[4 * BSTR]);
            }
#pragma unroll
            for (int mi = 0; mi < 4; mi++)
#pragma unroll
                for (int ni = 0; ni < 4; ni++)
                    mma_tf32(c[mi][ni], af[mi], bf[ni]);
        }
        __syncthreads();
        s ^= 1;
    }

    // epilogue
#pragma unroll
    for (int mi = 0; mi < 4; mi++) {
#pragma unroll
        for (int ni = 0; ni < 4; ni++) {
            long row = brow + m_base + 16 * mi + g;
            int  col = bcol + n_base + 8 * ni + 2 * t;
            *(float2*)&C[row * N + col]       = make_float2(c[mi][ni][0], c[mi][ni][1]);
            *(float2*)&C[(row + 8) * N + col] = make_float2(c[mi][ni][2], c[mi][ni][3]);
        }
    }
}

// =====================================================================
// RoPE table (double precision angles; tiny)
// =====================================================================
__global__ void rope_table() {
    int idx = blockIdx.x * 256 + threadIdx.x;
    if (idx >= TSEQ * 64) return;
    int d = idx & 63, t = idx >> 6;
    double inv = pow(10000.0, -(double)d / 64.0);
    double ang = (double)t * inv;
    g_cos[idx] = (float)cos(ang);
    g_sin[idx] = (float)sin(ang);
}

// x layout [B, T, nheads, 128]; rotate (d, d+64) pairs per head.
__global__ void rope_apply(float* __restrict__ x, int nheads, int total) {
    int idx = blockIdx.x * 256 + threadIdx.x;
    if (idx >= total) return;
    int d   = idx & 63;
    int bth = idx >> 6;
    int t   = (bth / nheads) % TSEQ;
    long base = (long)bth * 128 + d;
    float c = g_cos[t * 64 + d], s = g_sin[t * 64 + d];
    float x1 = x[base], x2 = x[base + 64];
    x[base]      = x1 * c - x2 * s;
    x[base + 64] = x1 * s + x2 * c;
}

// =====================================================================
// Flash attention (causal, GQA) — unchanged from R1 (SIMT fp32).
// =====================================================================
#define FLASH_SMEM_FLOATS (8192 + 8704 + 8448 + 4352 + 192)
#define FLASH_SMEM_BYTES  (FLASH_SMEM_FLOATS * 4)

__global__ __launch_bounds__(256) void flash_kernel() {
    extern __shared__ float sm[];
    float* Qs   = sm;              // 64*128
    float* Kt   = Qs + 8192;       // [128][68]
    float* Vs   = Kt + 8704;       // [64][132]
    float* Ss   = Vs + 8448;       // [64][68]
    float* mrow = Ss + 4352;
    float* lrow = mrow + 64;
    float* crow = lrow + 64;

    const int tid = threadIdx.x;
    const int qt  = blockIdx.x;
    const int bh  = blockIdx.y;
    const int b   = bh >> 5;
    const int h   = bh & 31;
    const int kvh = h >> 2;
    const int q0  = qt * 64;
    const int ty  = tid >> 4, tx = tid & 15;
    const int r0  = ty * 4;
    const int c0s = tx * 4;
    const int c0v = tx * 8;

    const float* Qg = g_Q + ((long)(b * TSEQ + q0)) * DIMC + h * DH;
#pragma unroll
    for (int it = 0; it < 8; it++) {
        int idx = it * 256 + tid;
        int row = idx >> 5;
        int dg  = (idx & 31) << 2;
        *(float4*)&Qs[row * 128 + dg] = *(const float4*)&Qg[(long)row * DIMC + dg];
    }
    if (tid < 64) { mrow[tid] = -1e30f; lrow[tid] = 0.f; }

    float o[4][8];
#pragma unroll
    for (int i = 0; i < 4; i++)
#pragma unroll
        for (int j = 0; j < 8; j++) o[i][j] = 0.f;

    const float scale = 0.0883883476483184f;

    for (int kt = 0; kt <= qt; kt++) {
        const int k0 = kt * 64;
        const float* Kg = g_K + ((long)(b * TSEQ + k0)) * KVDIM + kvh * DH;
        const float* Vg = g_V + ((long)(b * TSEQ + k0)) * KVDIM + kvh * DH;
#pragma unroll
        for (int it = 0; it < 8; it++) {
            int idx  = it * 256 + tid;
            int krow = idx >> 5;
            int dg   = (idx & 31) << 2;
            float4 kv = *(const float4*)&Kg[(long)krow * KVDIM + dg];
            Kt[(dg + 0) * 68 + krow] = kv.x;
            Kt[(dg + 1) * 68 + krow] = kv.y;
            Kt[(dg + 2) * 68 + krow] = kv.z;
            Kt[(dg + 3) * 68 + krow] = kv.w;
            *(float4*)&Vs[krow * 132 + dg] = *(const float4*)&Vg[(long)krow * KVDIM + dg];
        }
        __syncthreads();

        float s[4][4];
#pragma unroll
        for (int i = 0; i < 4; i++)
#pragma unroll
            for (int j = 0; j < 4; j++) s[i][j] = 0.f;

        for (int d = 0; d < 128; d += 4) {
            float q[4][4];
#pragma unroll
            for (int i = 0; i < 4; i++)
                *(float4*)&q[i][0] = *(float4*)&Qs[(r0 + i) * 128 + d];
#pragma unroll
            for (int dd = 0; dd < 4; dd++) {
                float4 kv = *(float4*)&Kt[(d + dd) * 68 + c0s];
                float kj[4] = {kv.x, kv.y, kv.z, kv.w};
#pragma unroll
                for (int i = 0; i < 4; i++) {
                    float qi = q[i][dd];
#pragma unroll
                    for (int j = 0; j < 4; j++) s[i][j] += qi * kj[j];
                }
            }
        }

#pragma unroll
        for (int i = 0; i < 4; i++) {
            int qi = q0 + r0 + i;
#pragma unroll
            for (int j = 0; j < 4; j++) {
                int ki = k0 + c0s + j;
                Ss[(r0 + i) * 68 + c0s + j] = (ki <= qi) ? s[i][j] * scale : -1e30f;
            }
        }
        __syncthreads();

        if (tid < 64) {
            float mo = mrow[tid];
            float mx = mo;
            float* srow = &Ss[tid * 68];
#pragma unroll 8
            for (int c = 0; c < 64; c++) mx = fmaxf(mx, srow[c]);
            float corr = __expf(mo - mx);
            float sum = 0.f;
#pragma unroll 8
            for (int c = 0; c < 64; c++) {
                float p = __expf(srow[c] - mx);
                srow[c] = p;
                sum += p;
            }
            mrow[tid] = mx;
            lrow[tid] = lrow[tid] * corr + sum;
            crow[tid] = corr;
        }
        __syncthreads();

#pragma unroll
        for (int i = 0; i < 4; i++) {
            float cf = crow[r0 + i];
#pragma unroll
            for (int j = 0; j < 8; j++) o[i][j] *= cf;
        }
#pragma unroll 4
        for (int k = 0; k < 64; k++) {
            float4 v0 = *(float4*)&Vs[k * 132 + c0v];
            float4 v1 = *(float4*)&Vs[k * 132 + c0v + 4];
#pragma unroll
            for (int i = 0; i < 4; i++) {
                float p = Ss[(r0 + i) * 68 + k];
                o[i][0] += p * v0.x; o[i][1] += p * v0.y;
                o[i][2] += p * v0.z; o[i][3] += p * v0.w;
                o[i][4] += p * v1.x; o[i][5] += p * v1.y;
                o[i][6] += p * v1.z; o[i][7] += p * v1.w;
            }
        }
        __syncthreads();
    }

    float* Og = g_O + ((long)(b * TSEQ + q0)) * DIMC + h * DH;
#pragma unroll
    for (int i = 0; i < 4; i++) {
        float inv = 1.f / lrow[r0 + i];
        float4 w0 = make_float4(o[i][0] * inv, o[i][1] * inv, o[i][2] * inv, o[i][3] * inv);
        float4 w1 = make_float4(o[i][4] * inv, o[i][5] * inv, o[i][6] * inv, o[i][7] * inv);
        *(float4*)&Og[(long)(r0 + i) * DIMC + c0v]     = w0;
        *(float4*)&Og[(long)(r0 + i) * DIMC + c0v + 4] = w1;
    }
}

// =====================================================================
// launch
// =====================================================================
extern "C" void kernel_launch(void* const* d_in, const int* in_sizes, int n_in,
                              void* d_out, int out_size) {
    const float* X  = (const float*)d_in[0];
    const float* Wq = (const float*)d_in[1];
    const float* Wk = (const float*)d_in[2];
    const float* Wv = (const float*)d_in[3];
    const float* Wo = (const float*)d_in[4];
    float* out = (float*)d_out;

    float *Qp, *Kp, *Vp, *Op;
    cudaGetSymbolAddress((void**)&Qp, g_Q);
    cudaGetSymbolAddress((void**)&Kp, g_K);
    cudaGetSymbolAddress((void**)&Vp, g_V);
    cudaGetSymbolAddress((void**)&Op, g_O);

    cudaFuncSetAttribute(flash_kernel, cudaFuncAttributeMaxDynamicSharedMemorySize,
                         FLASH_SMEM_BYTES);
    cudaFuncSetAttribute(gemm_tf32, cudaFuncAttributeMaxDynamicSharedMemorySize,
                         GEMM_SMEM_BYTES);

    rope_table<<<(TSEQ * 64 + 255) / 256, 256>>>();

    gemm_tf32<<<dim3(DIMC / 128, BT / 128), 256, GEMM_SMEM_BYTES>>>(X, Wq, Qp, BT, DIMC, DIMC);
    gemm_tf32<<<dim3(KVDIM / 128, BT / 128), 256, GEMM_SMEM_BYTES>>>(X, Wk, Kp, BT, KVDIM, DIMC);
    gemm_tf32<<<dim3(KVDIM / 128, BT / 128), 256, GEMM_SMEM_BYTES>>>(X, Wv, Vp, BT, KVDIM, DIMC);

    {
        int totq = BT * NH * 64;
        rope_apply<<<(totq + 255) / 256, 256>>>(Qp, NH, totq);
        int totk = BT * NKV * 64;
        rope_apply<<<(totk + 255) / 256, 256>>>(Kp, NKV, totk);
    }

    flash_kernel<<<dim3(TSEQ / 64, BB * NH), 256, FLASH_SMEM_BYTES>>>();

    gemm_tf32<<<dim3(DIMC / 128, BT / 128), 256, GEMM_SMEM_BYTES>>>(Op, Wo, out, BT, DIMC, DIMC);
}

// round 3
// speedup vs baseline: 3.3815x; 1.4631x over previous
#include <cuda_runtime.h>
#include <math.h>
#include <stdint.h>

#define DIMC   4096
#define NH     32
#define NKV    8
#define DH     128
#define BB     2
#define TSEQ   2048
#define BT     (BB * TSEQ)
#define KVDIM  (NKV * DH)

__device__ float g_Q[BT * DIMC];
__device__ float g_K[BT * KVDIM];
__device__ float g_V[BT * KVDIM];
__device__ float g_O[BT * DIMC];
__device__ float g_cos[TSEQ * 64];
__device__ float g_sin[TSEQ * 64];

// ---------------- common mma helpers ----------------
__device__ __forceinline__ uint32_t cvt_tf32(float f) {
    uint32_t u;
    asm("cvt.rna.tf32.f32 %0, %1;" : "=r"(u) : "f"(f));
    return u;
}
__device__ __forceinline__ void split_tf32(float x, uint32_t& hi, uint32_t& lo) {
    hi = cvt_tf32(x);
    lo = cvt_tf32(x - __uint_as_float(hi));
}
__device__ __forceinline__ void mma_tf32(float* c, const uint32_t* a, const uint32_t* b) {
    asm volatile(
        "mma.sync.aligned.m16n8k8.row.col.f32.tf32.tf32.f32 "
        "{%0,%1,%2,%3}, {%4,%5,%6,%7}, {%8,%9}, {%0,%1,%2,%3};"
        : "+f"(c[0]), "+f"(c[1]), "+f"(c[2]), "+f"(c[3])
        : "r"(a[0]), "r"(a[1]), "r"(a[2]), "r"(a[3]), "r"(b[0]), "r"(b[1]));
}
__device__ __forceinline__ void cpasync16(uint32_t dst, const void* src) {
    asm volatile("cp.async.cg.shared.global [%0], [%1], 16;" :: "r"(dst), "l"(src));
}

// =====================================================================
// TF32 GEMM (unchanged from R2)
// =====================================================================
#define GBM 128
#define GBN 128
#define GBK 32
#define ASTR 36
#define BSTR 136
#define GEMM_SMEM_BYTES ((2 * GBM * ASTR + 2 * GBK * BSTR) * 4)

__global__ __launch_bounds__(256) void gemm_tf32(const float* __restrict__ A,
                                                 const float* __restrict__ B,
                                                 float* __restrict__ C,
                                                 int M, int N, int K) {
    extern __shared__ float smem[];
    float* As = smem;
    float* Bs = smem + 2 * GBM * ASTR;

    const int tid  = threadIdx.x;
    const int brow = blockIdx.y * GBM;
    const int bcol = blockIdx.x * GBN;
    const int wid  = tid >> 5, lane = tid & 31;
    const int g    = lane >> 2, t = lane & 3;
    const int m_base = (wid & 1) * 64;
    const int n_base = (wid >> 1) * 32;

    const int a_r0 = tid >> 3;
    const int a_kc = (tid & 7) * 4;
    const int b_r0 = tid >> 5;
    const int b_nc = (tid & 31) * 4;

    float c[4][4][4];
#pragma unroll
    for (int mi = 0; mi < 4; mi++)
#pragma unroll
        for (int ni = 0; ni < 4; ni++)
#pragma unroll
            for (int r = 0; r < 4; r++) c[mi][ni][r] = 0.f;

    const int KT = K / GBK;
    {
        float* as = As;
        float* bs = Bs;
#pragma unroll
        for (int i = 0; i < 4; i++) {
            int r = a_r0 + 32 * i;
            cpasync16((uint32_t)__cvta_generic_to_shared(&as[r * ASTR + a_kc]),
                      A + (long)(brow + r) * K + a_kc);
        }
#pragma unroll
        for (int i = 0; i < 4; i++) {
            int r = b_r0 + 8 * i;
            cpasync16((uint32_t)__cvta_generic_to_shared(&bs[r * BSTR + b_nc]),
                      B + (long)r * N + bcol + b_nc);
        }
        asm volatile("cp.async.commit_group;");
    }

    int s = 0;
    for (int kt = 0; kt < KT; kt++) {
        if (kt + 1 < KT) {
            const int k0 = (kt + 1) * GBK;
            float* as = As + (s ^ 1) * GBM * ASTR;
            float* bs = Bs + (s ^ 1) * GBK * BSTR;
#pragma unroll
            for (int i = 0; i < 4; i++) {
                int r = a_r0 + 32 * i;
                cpasync16((uint32_t)__cvta_generic_to_shared(&as[r * ASTR + a_kc]),
                          A + (long)(brow + r) * K + k0 + a_kc);
            }
#pragma unroll
            for (int i = 0; i < 4; i++) {
                int r = b_r0 + 8 * i;
                cpasync16((uint32_t)__cvta_generic_to_shared(&bs[r * BSTR + b_nc]),
                          B + (long)(k0 + r) * N + bcol + b_nc);
            }
            asm volatile("cp.async.commit_group;");
            asm volatile("cp.async.wait_group 1;");
        } else {
            asm volatile("cp.async.wait_group 0;");
        }
        __syncthreads();

        const float* as = As + s * GBM * ASTR;
        const float* bs = Bs + s * GBK * BSTR;
#pragma unroll
        for (int kk = 0; kk < GBK; kk += 8) {
            uint32_t af[4][4], bf[4][2];
#pragma unroll
            for (int mi = 0; mi < 4; mi++) {
                const float* p = &as[(m_base + 16 * mi + g) * ASTR + kk + t];
                af[mi][0] = cvt_tf32(p[0]);
                af[mi][1] = cvt_tf32(p[8 * ASTR]);
                af[mi][2] = cvt_tf32(p[4]);
                af[mi][3] = cvt_tf32(p[8 * ASTR + 4]);
            }
#pragma unroll
            for (int ni = 0; ni < 4; ni++) {
                const float* p = &bs[(kk + t) * BSTR + n_base + 8 * ni + g];
                bf[ni][0] = cvt_tf32(p[0]);
                bf[ni][1] = cvt_tf32(p[4 * BSTR]);
            }
#pragma unroll
            for (int mi = 0; mi < 4; mi++)
#pragma unroll
                for (int ni = 0; ni < 4; ni++)
                    mma_tf32(c[mi][ni], af[mi], bf[ni]);
        }
        __syncthreads();
        s ^= 1;
    }

#pragma unroll
    for (int mi = 0; mi < 4; mi++) {
#pragma unroll
        for (int ni = 0; ni < 4; ni++) {
            long row = brow + m_base + 16 * mi + g;
            int  col = bcol + n_base + 8 * ni + 2 * t;
            *(float2*)&C[row * N + col]       = make_float2(c[mi][ni][0], c[mi][ni][1]);
            *(float2*)&C[(row + 8) * N + col] = make_float2(c[mi][ni][2], c[mi][ni][3]);
        }
    }
}

// =====================================================================
// RoPE (unchanged)
// =====================================================================
__global__ void rope_table() {
    int idx = blockIdx.x * 256 + threadIdx.x;
    if (idx >= TSEQ * 64) return;
    int d = idx & 63, t = idx >> 6;
    double inv = pow(10000.0, -(double)d / 64.0);
    double ang = (double)t * inv;
    g_cos[idx] = (float)cos(ang);
    g_sin[idx] = (float)sin(ang);
}

__global__ void rope_apply(float* __restrict__ x, int nheads, int total) {
    int idx = blockIdx.x * 256 + threadIdx.x;
    if (idx >= total) return;
    int d   = idx & 63;
    int bth = idx >> 6;
    int t   = (bth / nheads) % TSEQ;
    long base = (long)bth * 128 + d;
    float c = g_cos[t * 64 + d], s = g_sin[t * 64 + d];
    float x1 = x[base], x2 = x[base + 64];
    x[base]      = x1 * c - x2 * s;
    x[base + 64] = x1 * s + x2 * c;
}

// =====================================================================
// Tensor-core flash attention, 3xTF32 (fp32-equivalent accuracy).
// CTA: 64 Q rows, kt tiles of 64 keys. 8 warps: wm=wid&3 (16 rows each),
// wn=wid>>2 (S: 32-key half; PV: 64-dh half).
// =====================================================================
#define FSTR_QK 132   // ≡4 mod 32 -> conflict-free A/B frag loads
#define FSTR_V  136   // ≡8 mod 32 -> conflict-free V B-frag loads
#define FSTR_P  68    // ≡4 mod 32 -> conflict-free P A-frag loads

#define QLO_OFF  0
#define KHI_OFF  (QLO_OFF + 64 * FSTR_QK)
#define KLO_OFF  (KHI_OFF + 64 * FSTR_QK)
#define VHI_OFF  (KLO_OFF + 64 * FSTR_QK)
#define VLO_OFF  (VHI_OFF + 64 * FSTR_V)
#define PHI_OFF  (VLO_OFF + 64 * FSTR_V)
#define PLO_OFF  (PHI_OFF + 64 * FSTR_P)
#define MROW_OFF (PLO_OFF + 64 * FSTR_P)
#define LROW_OFF (MROW_OFF + 64)
#define PMAX_OFF (LROW_OFF + 64)
#define PSUM_OFF (PMAX_OFF + 128)
#define FLASH_TC_FLOATS (PSUM_OFF + 128)
#define FLASH_TC_BYTES  (FLASH_TC_FLOATS * 4)

__global__ __launch_bounds__(256, 1) void flash_tc() {
    extern __shared__ float sm[];
    float* Qlo  = sm + QLO_OFF;
    float* Khi  = sm + KHI_OFF;
    float* Klo  = sm + KLO_OFF;
    float* Vhi  = sm + VHI_OFF;
    float* Vlo  = sm + VLO_OFF;
    float* Phi  = sm + PHI_OFF;
    float* Plo  = sm + PLO_OFF;
    float* mrow = sm + MROW_OFF;
    float* lrow = sm + LROW_OFF;
    float* pmax = sm + PMAX_OFF;
    float* psum = sm + PSUM_OFF;

    const int tid = threadIdx.x;
    const int qt  = blockIdx.x;
    const int bh  = blockIdx.y;
    const int b   = bh >> 5;
    const int h   = bh & 31;
    const int kvh = h >> 2;
    const int q0  = qt * 64;
    const int lane = tid & 31, wid = tid >> 5;
    const int g = lane >> 2, t = lane & 3;
    const int wm = wid & 3, wn = wid >> 2;
    const int r0 = wm * 16 + g;

    // ---- stage Q (rope'd) into Khi temp, init stats ----
    const float* Qg = g_Q + ((long)(b * TSEQ + q0)) * DIMC + h * DH;
#pragma unroll
    for (int it = 0; it < 8; it++) {
        int idx = it * 256 + tid;
        int row = idx >> 5, c4 = (idx & 31) << 2;
        *(float4*)&Khi[row * FSTR_QK + c4] = *(const float4*)&Qg[(long)row * DIMC + c4];
    }
    if (tid < 64) { mrow[tid] = -1e30f; lrow[tid] = 0.f; }
    __syncthreads();

    // ---- Q frags: hi in regs (scale folded in), lo -> Qlo smem ----
    const float scale = 0.0883883476483184f;
    uint32_t qhi[16][4];
    uint32_t qlo[16][4];
#pragma unroll
    for (int kk = 0; kk < 16; kk++) {
        const int c = kk * 8 + t;
        float v0 = Khi[r0 * FSTR_QK + c] * scale;
        float v1 = Khi[(r0 + 8) * FSTR_QK + c] * scale;
        float v2 = Khi[r0 * FSTR_QK + c + 4] * scale;
        float v3 = Khi[(r0 + 8) * FSTR_QK + c + 4] * scale;
        split_tf32(v0, qhi[kk][0], qlo[kk][0]);
        split_tf32(v1, qhi[kk][1], qlo[kk][1]);
        split_tf32(v2, qhi[kk][2], qlo[kk][2]);
        split_tf32(v3, qhi[kk][3], qlo[kk][3]);
    }
    __syncthreads();   // all reads of Khi-staged Q done
    if (wn == 0) {
#pragma unroll
        for (int kk = 0; kk < 16; kk++) {
            const int c = kk * 8 + t;
            Qlo[r0 * FSTR_QK + c]           = __uint_as_float(qlo[kk][0]);
            Qlo[(r0 + 8) * FSTR_QK + c]     = __uint_as_float(qlo[kk][1]);
            Qlo[r0 * FSTR_QK + c + 4]       = __uint_as_float(qlo[kk][2]);
            Qlo[(r0 + 8) * FSTR_QK + c + 4] = __uint_as_float(qlo[kk][3]);
        }
    }

    float oc[8][4];
#pragma unroll
    for (int nt = 0; nt < 8; nt++)
#pragma unroll
        for (int r = 0; r < 4; r++) oc[nt][r] = 0.f;

    for (int kt = 0; kt <= qt; kt++) {
        const int k0 = kt * 64;
        const float* Kg = g_K + ((long)(b * TSEQ + k0)) * KVDIM + kvh * DH;
        const float* Vg = g_V + ((long)(b * TSEQ + k0)) * KVDIM + kvh * DH;

        __syncthreads();   // previous tile's smem reads done (also covers Qlo stores)
#pragma unroll
        for (int it = 0; it < 8; it++) {
            int idx = it * 256 + tid;
            int row = idx >> 5, c4 = (idx & 31) << 2;
            float4 kq = *(const float4*)&Kg[(long)row * KVDIM + c4];
            float4 vq = *(const float4*)&Vg[(long)row * KVDIM + c4];
            uint32_t h0, h1, h2, h3, l0, l1, l2, l3;
            split_tf32(kq.x, h0, l0); split_tf32(kq.y, h1, l1);
            split_tf32(kq.z, h2, l2); split_tf32(kq.w, h3, l3);
            *(float4*)&Khi[row * FSTR_QK + c4] = make_float4(
                __uint_as_float(h0), __uint_as_float(h1), __uint_as_float(h2), __uint_as_float(h3));
            *(float4*)&Klo[row * FSTR_QK + c4] = make_float4(
                __uint_as_float(l0), __uint_as_float(l1), __uint_as_float(l2), __uint_as_float(l3));
            split_tf32(vq.x, h0, l0); split_tf32(vq.y, h1, l1);
            split_tf32(vq.z, h2, l2); split_tf32(vq.w, h3, l3);
            *(float4*)&Vhi[row * FSTR_V + c4] = make_float4(
                __uint_as_float(h0), __uint_as_float(h1), __uint_as_float(h2), __uint_as_float(h3));
            *(float4*)&Vlo[row * FSTR_V + c4] = make_float4(
                __uint_as_float(l0), __uint_as_float(l1), __uint_as_float(l2), __uint_as_float(l3));
        }
        __syncthreads();

        // ---- S = Q K^T (3xTF32) ----
        float sc[4][4];
#pragma unroll
        for (int nt = 0; nt < 4; nt++)
#pragma unroll
            for (int r = 0; r < 4; r++) sc[nt][r] = 0.f;

#pragma unroll
        for (int kk = 0; kk < 16; kk++) {
            const int c = kk * 8 + t;
#pragma unroll
            for (int nt = 0; nt < 4; nt++) {
                const int kr = wn * 32 + nt * 8 + g;
                uint32_t bhf[2], blf[2];
                bhf[0] = __float_as_uint(Khi[kr * FSTR_QK + c]);
                bhf[1] = __float_as_uint(Khi[kr * FSTR_QK + c + 4]);
                blf[0] = __float_as_uint(Klo[kr * FSTR_QK + c]);
                blf[1] = __float_as_uint(Klo[kr * FSTR_QK + c + 4]);
                mma_tf32(sc[nt], qhi[kk], bhf);
                mma_tf32(sc[nt], qlo[kk], bhf);
                mma_tf32(sc[nt], qhi[kk], blf);
            }
        }

        // ---- causal mask (diagonal tile only) ----
        if (kt == qt) {
#pragma unroll
            for (int nt = 0; nt < 4; nt++) {
                int c = wn * 32 + nt * 8 + 2 * t;
                if (c     > r0)     sc[nt][0] = -1e30f;
                if (c + 1 > r0)     sc[nt][1] = -1e30f;
                if (c     > r0 + 8) sc[nt][2] = -1e30f;
                if (c + 1 > r0 + 8) sc[nt][3] = -1e30f;
            }
        }

        // ---- online softmax ----
        float mx0 = -1e30f, mx1 = -1e30f;
#pragma unroll
        for (int nt = 0; nt < 4; nt++) {
            mx0 = fmaxf(mx0, fmaxf(sc[nt][0], sc[nt][1]));
            mx1 = fmaxf(mx1, fmaxf(sc[nt][2], sc[nt][3]));
        }
        mx0 = fmaxf(mx0, __shfl_xor_sync(0xffffffffu, mx0, 1));
        mx0 = fmaxf(mx0, __shfl_xor_sync(0xffffffffu, mx0, 2));
        mx1 = fmaxf(mx1, __shfl_xor_sync(0xffffffffu, mx1, 1));
        mx1 = fmaxf(mx1, __shfl_xor_sync(0xffffffffu, mx1, 2));
        if (t == 0) {
            pmax[wn * 64 + r0]     = mx0;
            pmax[wn * 64 + r0 + 8] = mx1;
        }
        __syncthreads();
        float mold0 = mrow[r0], mold1 = mrow[r0 + 8];
        float mnew0 = fmaxf(mold0, fmaxf(pmax[r0], pmax[64 + r0]));
        float mnew1 = fmaxf(mold1, fmaxf(pmax[r0 + 8], pmax[64 + r0 + 8]));
        float corr0 = __expf(mold0 - mnew0);
        float corr1 = __expf(mold1 - mnew1);

        float sum0 = 0.f, sum1 = 0.f;
#pragma unroll
        for (int nt = 0; nt < 4; nt++) {
            float p00 = __expf(sc[nt][0] - mnew0);
            float p01 = __expf(sc[nt][1] - mnew0);
            float p10 = __expf(sc[nt][2] - mnew1);
            float p11 = __expf(sc[nt][3] - mnew1);
            sum0 += p00 + p01;
            sum1 += p10 + p11;
            uint32_t h00, h01, h10, h11, l00, l01, l10, l11;
            split_tf32(p00, h00, l00); split_tf32(p01, h01, l01);
            split_tf32(p10, h10, l10); split_tf32(p11, h11, l11);
            int c = wn * 32 + nt * 8 + 2 * t;
            *(float2*)&Phi[r0 * FSTR_P + c] =
                make_float2(__uint_as_float(h00), __uint_as_float(h01));
            *(float2*)&Plo[r0 * FSTR_P + c] =
                make_float2(__uint_as_float(l00), __uint_as_float(l01));
            *(float2*)&Phi[(r0 + 8) * FSTR_P + c] =
                make_float2(__uint_as_float(h10), __uint_as_float(h11));
            *(float2*)&Plo[(r0 + 8) * FSTR_P + c] =
                make_float2(__uint_as_float(l10), __uint_as_float(l11));
        }
        sum0 += __shfl_xor_sync(0xffffffffu, sum0, 1);
        sum0 += __shfl_xor_sync(0xffffffffu, sum0, 2);
        sum1 += __shfl_xor_sync(0xffffffffu, sum1, 1);
        sum1 += __shfl_xor_sync(0xffffffffu, sum1, 2);
        if (t == 0) {
            psum[wn * 64 + r0]     = sum0;
            psum[wn * 64 + r0 + 8] = sum1;
        }

        // rescale O accumulators
#pragma unroll
        for (int nt = 0; nt < 8; nt++) {
            oc[nt][0] *= corr0; oc[nt][1] *= corr0;
            oc[nt][2] *= corr1; oc[nt][3] *= corr1;
        }
        __syncthreads();
        if (wn == 0 && t == 0) {
            mrow[r0] = mnew0;
            mrow[r0 + 8] = mnew1;
            lrow[r0]     = lrow[r0] * corr0 + psum[r0] + psum[64 + r0];
            lrow[r0 + 8] = lrow[r0 + 8] * corr1 + psum[r0 + 8] + psum[64 + r0 + 8];
        }

        // ---- O += P V (3xTF32) ----
#pragma unroll
        for (int kk = 0; kk < 8; kk++) {
            const int c = kk * 8 + t;
            uint32_t ph[4], pl[4];
            ph[0] = __float_as_uint(Phi[r0 * FSTR_P + c]);
            ph[1] = __float_as_uint(Phi[(r0 + 8) * FSTR_P + c]);
            ph[2] = __float_as_uint(Phi[r0 * FSTR_P + c + 4]);
            ph[3] = __float_as_uint(Phi[(r0 + 8) * FSTR_P + c + 4]);
            pl[0] = __float_as_uint(Plo[r0 * FSTR_P + c]);
            pl[1] = __float_as_uint(Plo[(r0 + 8) * FSTR_P + c]);
            pl[2] = __float_as_uint(Plo[r0 * FSTR_P + c + 4]);
            pl[3] = __float_as_uint(Plo[(r0 + 8) * FSTR_P + c + 4]);
#pragma unroll
            for (int nt = 0; nt < 8; nt++) {
                const int vc = wn * 64 + nt * 8 + g;
                uint32_t vh[2], vl[2];
                vh[0] = __float_as_uint(Vhi[(kk * 8 + t) * FSTR_V + vc]);
                vh[1] = __float_as_uint(Vhi[(kk * 8 + t + 4) * FSTR_V + vc]);
                vl[0] = __float_as_uint(Vlo[(kk * 8 + t) * FSTR_V + vc]);
                vl[1] = __float_as_uint(Vlo[(kk * 8 + t + 4) * FSTR_V + vc]);
                mma_tf32(oc[nt], ph, vh);
                mma_tf32(oc[nt], pl, vh);
                mma_tf32(oc[nt], ph, vl);
            }
        }
    }

    __syncthreads();
    float linv0 = 1.f / lrow[r0];
    float linv1 = 1.f / lrow[r0 + 8];
    float* Og = g_O + ((long)(b * TSEQ + q0)) * DIMC + h * DH;
#pragma unroll
    for (int nt = 0; nt < 8; nt++) {
        int c = wn * 64 + nt * 8 + 2 * t;
        *(float2*)&Og[(long)r0 * DIMC + c] =
            make_float2(oc[nt][0] * linv0, oc[nt][1] * linv0);
        *(float2*)&Og[(long)(r0 + 8) * DIMC + c] =
            make_float2(oc[nt][2] * linv1, oc[nt][3] * linv1);
    }
}

// =====================================================================
// launch
// =====================================================================
extern "C" void kernel_launch(void* const* d_in, const int* in_sizes, int n_in,
                              void* d_out, int out_size) {
    const float* X  = (const float*)d_in[0];
    const float* Wq = (const float*)d_in[1];
    const float* Wk = (const float*)d_in[2];
    const float* Wv = (const float*)d_in[3];
    const float* Wo = (const float*)d_in[4];
    float* out = (float*)d_out;

    float *Qp, *Kp, *Vp, *Op;
    cudaGetSymbolAddress((void**)&Qp, g_Q);
    cudaGetSymbolAddress((void**)&Kp, g_K);
    cudaGetSymbolAddress((void**)&Vp, g_V);
    cudaGetSymbolAddress((void**)&Op, g_O);

    cudaFuncSetAttribute(gemm_tf32, cudaFuncAttributeMaxDynamicSharedMemorySize,
                         GEMM_SMEM_BYTES);
    cudaFuncSetAttribute(flash_tc, cudaFuncAttributeMaxDynamicSharedMemorySize,
                         FLASH_TC_BYTES);

    rope_table<<<(TSEQ * 64 + 255) / 256, 256>>>();

    gemm_tf32<<<dim3(DIMC / 128, BT / 128), 256, GEMM_SMEM_BYTES>>>(X, Wq, Qp, BT, DIMC, DIMC);
    gemm_tf32<<<dim3(KVDIM / 128, BT / 128), 256, GEMM_SMEM_BYTES>>>(X, Wk, Kp, BT, KVDIM, DIMC);
    gemm_tf32<<<dim3(KVDIM / 128, BT / 128), 256, GEMM_SMEM_BYTES>>>(X, Wv, Vp, BT, KVDIM, DIMC);

    {
        int totq = BT * NH * 64;
        rope_apply<<<(totq + 255) / 256, 256>>>(Qp, NH, totq);
        int totk = BT * NKV * 64;
        rope_apply<<<(totk + 255) / 256, 256>>>(Kp, NKV, totk);
    }

    flash_tc<<<dim3(TSEQ / 64, BB * NH), 256, FLASH_TC_BYTES>>>();

    gemm_tf32<<<dim3(DIMC / 128, BT / 128), 256, GEMM_SMEM_BYTES>>>(Op, Wo, out, BT, DIMC, DIMC);
}